// round 7
// baseline (speedup 1.0000x reference)
#include <cuda_runtime.h>
#include <cuda_fp16.h>
#include <cstdint>

// ============================================================================
// y[8192,4096] = x[8192,4096] @ sign(W)[4096,4096], fp32 in/out.
// Plain-sm_103 target (no tcgen05). Pipelined HMMA GEMM, 128x256 CTA tile,
// warp tile 64x64, TK=128, 2 stages.
// R7 (= R6 + compile fix): warp-specialized producers (2 warps) fuse the
// x->fp16 conversion into the GEMM (LDG fp32 -> CVT -> STS swizzled),
// eliminating k_cvt_x (-28us DRAM kernel, net -128MB DRAM).
// ============================================================================

#define MM 8192
#define NN 4096
#define KK 4096

#define TM 128
#define TN 256
#define TK 128                     // K elems per stage (256B per row)
#define NK (KK / TK)               // 32

#define A_STAGE_BYTES (TM * TK * 2)            // 32768
#define B_STAGE_BYTES (TN * TK * 2)            // 65536
#define SMEM_TOTAL (2 * (A_STAGE_BYTES + B_STAGE_BYTES))  // 196608

#define NTHREADS 320               // 8 compute warps + 2 producer warps

__device__ __align__(1024) __half g_sh[(size_t)NN * KK];   // sign(W)^T fp16, [N][K]

// ---------------------------------------------------------------------------
__device__ __forceinline__ uint32_t smem_u32(const void* p) {
    uint32_t a;
    asm("{ .reg .u64 t; cvta.to.shared.u64 t, %1; cvt.u32.u64 %0, t; }"
        : "=r"(a) : "l"(p));
    return a;
}

__device__ __forceinline__ uint32_t h2_u32(__half2 h) {
    return reinterpret_cast<uint32_t&>(h);
}

#define CP_ASYNC_CG(dst, src) \
    asm volatile("cp.async.cg.shared.global [%0], [%1], 16;" \
        :: "r"((uint32_t)(dst)), "l"(src) : "memory")
#define CP_COMMIT() asm volatile("cp.async.commit_group;" ::: "memory")
#define CP_WAIT(n)  asm volatile("cp.async.wait_group %0;" :: "n"(n) : "memory")

#define STS128(addr, r0, r1, r2, r3) \
    asm volatile("st.shared.v4.b32 [%0], {%1,%2,%3,%4};" \
        :: "r"((uint32_t)(addr)), "r"(r0), "r"(r1), "r"(r2), "r"(r3) : "memory")

__device__ __forceinline__ void ldsm4(uint32_t* r, uint32_t addr) {
    asm volatile("ldmatrix.sync.aligned.m8n8.x4.shared.b16 {%0,%1,%2,%3}, [%4];"
        : "=r"(r[0]), "=r"(r[1]), "=r"(r[2]), "=r"(r[3]) : "r"(addr));
}

__device__ __forceinline__ void mma16816(float* c, const uint32_t* a, const uint32_t* b) {
    asm volatile(
        "mma.sync.aligned.m16n8k16.row.col.f32.f16.f16.f32 "
        "{%0,%1,%2,%3}, {%4,%5,%6,%7}, {%8,%9}, {%0,%1,%2,%3};"
        : "+f"(c[0]), "+f"(c[1]), "+f"(c[2]), "+f"(c[3])
        : "r"(a[0]), "r"(a[1]), "r"(a[2]), "r"(a[3]), "r"(b[0]), "r"(b[1]));
}

// ---------------------------------------------------------------------------
// o[n][k] = sign(W[k][n]) fp16; 64x64 tiles -> 128B coalesced output rows
__global__ void k_sign_t(const float* __restrict__ W, __half* __restrict__ o) {
    __shared__ float t[64][65];
    int n0 = blockIdx.x * 64, k0 = blockIdx.y * 64;
    int tx = threadIdx.x, ty = threadIdx.y;    // (64, 4)
#pragma unroll
    for (int j = 0; j < 64; j += 4)
        t[ty + j][tx] = W[(size_t)(k0 + ty + j) * NN + n0 + tx];
    __syncthreads();
#pragma unroll
    for (int j = 0; j < 64; j += 4) {
        float v = t[tx][ty + j];
        float s = (v > 0.f) ? 1.f : ((v < 0.f) ? -1.f : 0.f);
        o[(size_t)(n0 + ty + j) * KK + k0 + tx] = __float2half(s);
    }
}

// ---------------------------------------------------------------------------
// GEMM: warps 0-7 compute (2M x 4N, warp tile 64x64); warps 8-9 produce
// (B cp.async + A fp32->fp16 conversion into swizzled smem, 1 stage ahead).
// ---------------------------------------------------------------------------
__global__ __launch_bounds__(NTHREADS, 1) void gemm_kernel(
    const float* __restrict__ x, float* __restrict__ out)
{
    extern __shared__ char smem[];
    const uint32_t sA0 = smem_u32(smem);
    const uint32_t sB0 = sA0 + 2 * A_STAGE_BYTES;

    const int tid = threadIdx.x;
    const int wid = tid >> 5;
    const int lane = tid & 31;

    const int TILES_N = NN / TN;   // 16
    const int GROUP_M = 8;
    int bid = blockIdx.x;
    int group = bid / (GROUP_M * TILES_N);
    int rem = bid % (GROUP_M * TILES_N);
    int pm = group * GROUP_M + (rem % GROUP_M);
    int pn = rem / GROUP_M;
    const int m0 = pm * TM;
    const int n0 = pn * TN;

    if (wid >= 8) {
        // =================== producer warps (64 threads) ===================
        const int lt = tid - 256;                       // 0..63
        const float*  gA = x    + (size_t)m0 * KK;      // fp32 A rows
        const __half* gB = g_sh + (size_t)n0 * KK;      // fp16 B rows

        // Convert A tile for k-iter `it` into stage `s` (LDG fp32 -> STS fp16)
        auto cvtA = [&](int s, int it) {
            uint32_t sa = sA0 + s * A_STAGE_BYTES;
            const float* ga = gA + (size_t)it * TK;
#pragma unroll
            for (int i = 0; i < 32; ++i) {              // 2048 16B-chunks / 64 thr
                int idx = lt + i * 64;
                int row = idx >> 4, c = idx & 15;
                const float4* src = reinterpret_cast<const float4*>(
                    ga + (size_t)row * KK + c * 8);
                float4 v0 = src[0];
                float4 v1 = src[1];
                __half2 h0 = __floats2half2_rn(v0.x, v0.y);
                __half2 h1 = __floats2half2_rn(v0.z, v0.w);
                __half2 h2 = __floats2half2_rn(v1.x, v1.y);
                __half2 h3 = __floats2half2_rn(v1.z, v1.w);
                int sc = c ^ (row & 7);
                STS128(sa + row * 256 + sc * 16,
                       h2_u32(h0), h2_u32(h1), h2_u32(h2), h2_u32(h3));
            }
        };
        auto loadB = [&](int s, int it) {
            uint32_t sb = sB0 + s * B_STAGE_BYTES;
            const __half* gb = gB + (size_t)it * TK;
#pragma unroll
            for (int i = 0; i < 64; ++i) {              // 4096 16B-chunks / 64 thr
                int idx = lt + i * 64;
                int row = idx >> 4, c = idx & 15;
                int sc = c ^ (row & 7);
                CP_ASYNC_CG(sb + row * 256 + sc * 16, gb + (size_t)row * KK + c * 8);
            }
        };

        // prologue: stage 0
        loadB(0, 0);
        CP_COMMIT();
        cvtA(0, 0);

        for (int it = 0; it < NK; ++it) {
            CP_WAIT(0);
            __syncthreads();                // publish stage it&1; stage (it+1)&1 free
            if (it + 1 < NK) {
                int sn = (it + 1) & 1;
                loadB(sn, it + 1);
                CP_COMMIT();
                cvtA(sn, it + 1);
            }
        }
        return;   // producers exit; no further syncs anywhere
    }

    // ===================== compute warps (256 threads) =====================
    const int wm = wid & 1;
    const int wn = wid >> 1;

    const int a_row_base = wm * 64 + (lane & 15);
    const int a_hi = lane >> 4;
    const int b_n_base = wn * 64 + (lane & 7) + ((lane >> 4) << 3);
    const int b_hi = (lane >> 3) & 1;

    float acc[4][8][4];
#pragma unroll
    for (int mt = 0; mt < 4; ++mt)
#pragma unroll
        for (int nf = 0; nf < 8; ++nf)
#pragma unroll
            for (int v = 0; v < 4; ++v) acc[mt][nf][v] = 0.f;

    for (int it = 0; it < NK; ++it) {
        __syncthreads();                    // stage s data (A STS + B cp.async) visible
        const int s = it & 1;
        const uint32_t sa = sA0 + s * A_STAGE_BYTES;
        const uint32_t sb = sB0 + s * B_STAGE_BYTES;

#pragma unroll
        for (int ks = 0; ks < 8; ++ks) {
            uint32_t a[4][4], b[4][4];
#pragma unroll
            for (int mt = 0; mt < 4; ++mt) {
                int row = a_row_base + mt * 16;
                int ch = ks * 2 + a_hi;
                ldsm4(a[mt], sa + row * 256 + ((ch ^ (row & 7)) << 4));
            }
#pragma unroll
            for (int bq = 0; bq < 4; ++bq) {
                int n = b_n_base + bq * 16;
                int ch = ks * 2 + b_hi;
                ldsm4(b[bq], sb + n * 256 + ((ch ^ (n & 7)) << 4));
            }
#pragma unroll
            for (int mt = 0; mt < 4; ++mt)
#pragma unroll
                for (int nf = 0; nf < 8; ++nf)
                    mma16816(acc[mt][nf], a[mt], &b[nf >> 1][(nf & 1) * 2]);
        }
    }

    // epilogue
#pragma unroll
    for (int mt = 0; mt < 4; ++mt) {
        int r0 = m0 + wm * 64 + mt * 16 + (lane >> 2);
#pragma unroll
        for (int nf = 0; nf < 8; ++nf) {
            int c0 = n0 + wn * 64 + nf * 8 + (lane & 3) * 2;
            float2 v0 = make_float2(acc[mt][nf][0], acc[mt][nf][1]);
            float2 v1 = make_float2(acc[mt][nf][2], acc[mt][nf][3]);
            *reinterpret_cast<float2*>(out + (size_t)r0 * NN + c0) = v0;
            *reinterpret_cast<float2*>(out + (size_t)(r0 + 8) * NN + c0) = v1;
        }
    }
}

// ---------------------------------------------------------------------------
extern "C" void kernel_launch(void* const* d_in, const int* in_sizes, int n_in,
                              void* d_out, int out_size) {
    const float* x;
    const float* W;
    if (in_sizes[0] == MM * KK) {
        x = (const float*)d_in[0];
        W = (const float*)d_in[1];
    } else {
        x = (const float*)d_in[1];
        W = (const float*)d_in[0];
    }

    void* sh_ptr = nullptr;
    cudaGetSymbolAddress(&sh_ptr, g_sh);

    {
        dim3 g(NN / 64, KK / 64), b(64, 4);
        k_sign_t<<<g, b>>>(W, (__half*)sh_ptr);
    }

    cudaFuncSetAttribute(gemm_kernel, cudaFuncAttributeMaxDynamicSharedMemorySize, SMEM_TOTAL);
    int n_tiles = (MM / TM) * (NN / TN);   // 1024
    gemm_kernel<<<n_tiles, NTHREADS, SMEM_TOTAL>>>(x, (float*)d_out);
}

// round 8
// speedup vs baseline: 3.2053x; 3.2053x over previous
#include <cuda_runtime.h>
#include <cuda_fp16.h>
#include <cstdint>

// ============================================================================
// y[8192,4096] = x[8192,4096] @ sign(W)[4096,4096], fp32 in/out.
// Plain-sm_103 target (no tcgen05). Pipelined HMMA GEMM.
// R8: 512 threads / 16 warps (2M x 8N), warp tile 64x32, CTA tile 128x256,
// TK=128, 2 stages. Doubles warps/SMSP (2->4) to overlap LDSM bursts with
// MMA across warps (R5 showed ~no overlap at 8 warps). Same gmem traffic.
// Conversion kernels kept separate (R7 fusion serialized the pipeline).
// ============================================================================

#define MM 8192
#define NN 4096
#define KK 4096

#define TM 128
#define TN 256
#define TK 128                     // K elems per stage (256B per row)
#define NK (KK / TK)               // 32

#define A_STAGE_BYTES (TM * TK * 2)            // 32768
#define B_STAGE_BYTES (TN * TK * 2)            // 65536
#define SMEM_TOTAL (2 * (A_STAGE_BYTES + B_STAGE_BYTES))  // 196608

#define NTHREADS 512

__device__ __align__(1024) __half g_xh[(size_t)MM * KK];   // x as fp16, [M][K]
__device__ __align__(1024) __half g_sh[(size_t)NN * KK];   // sign(W)^T fp16, [N][K]

// ---------------------------------------------------------------------------
__device__ __forceinline__ uint32_t smem_u32(const void* p) {
    uint32_t a;
    asm("{ .reg .u64 t; cvta.to.shared.u64 t, %1; cvt.u32.u64 %0, t; }"
        : "=r"(a) : "l"(p));
    return a;
}

#define CP_ASYNC_CG(dst, src) \
    asm volatile("cp.async.cg.shared.global [%0], [%1], 16;" \
        :: "r"((uint32_t)(dst)), "l"(src) : "memory")
#define CP_COMMIT() asm volatile("cp.async.commit_group;" ::: "memory")
#define CP_WAIT(n)  asm volatile("cp.async.wait_group %0;" :: "n"(n) : "memory")

__device__ __forceinline__ void ldsm4(uint32_t* r, uint32_t addr) {
    asm volatile("ldmatrix.sync.aligned.m8n8.x4.shared.b16 {%0,%1,%2,%3}, [%4];"
        : "=r"(r[0]), "=r"(r[1]), "=r"(r[2]), "=r"(r[3]) : "r"(addr));
}

__device__ __forceinline__ void mma16816(float* c, const uint32_t* a, const uint32_t* b) {
    asm volatile(
        "mma.sync.aligned.m16n8k16.row.col.f32.f16.f16.f32 "
        "{%0,%1,%2,%3}, {%4,%5,%6,%7}, {%8,%9}, {%0,%1,%2,%3};"
        : "+f"(c[0]), "+f"(c[1]), "+f"(c[2]), "+f"(c[3])
        : "r"(a[0]), "r"(a[1]), "r"(a[2]), "r"(a[3]), "r"(b[0]), "r"(b[1]));
}

// ---------------------------------------------------------------------------
struct h8_t { __half2 a, b, c, d; };   // 16B

__global__ void k_cvt_x(const float4* __restrict__ x, h8_t* __restrict__ o, int n8) {
    int i = blockIdx.x * blockDim.x + threadIdx.x;
    if (i < n8) {
        float4 v0 = x[2 * i];
        float4 v1 = x[2 * i + 1];
        h8_t h;
        h.a = __floats2half2_rn(v0.x, v0.y);
        h.b = __floats2half2_rn(v0.z, v0.w);
        h.c = __floats2half2_rn(v1.x, v1.y);
        h.d = __floats2half2_rn(v1.z, v1.w);
        o[i] = h;
    }
}

// o[n][k] = sign(W[k][n]) fp16; 64x64 tiles -> 128B coalesced output rows
__global__ void k_sign_t(const float* __restrict__ W, __half* __restrict__ o) {
    __shared__ float t[64][65];
    int n0 = blockIdx.x * 64, k0 = blockIdx.y * 64;
    int tx = threadIdx.x, ty = threadIdx.y;    // (64, 4)
#pragma unroll
    for (int j = 0; j < 64; j += 4)
        t[ty + j][tx] = W[(size_t)(k0 + ty + j) * NN + n0 + tx];
    __syncthreads();
#pragma unroll
    for (int j = 0; j < 64; j += 4) {
        float v = t[tx][ty + j];
        float s = (v > 0.f) ? 1.f : ((v < 0.f) ? -1.f : 0.f);
        o[(size_t)(n0 + ty + j) * KK + k0 + tx] = __float2half(s);
    }
}

// ---------------------------------------------------------------------------
// GEMM: 128x256 CTA tile, 16 warps (2M x 8N), warp tile 64x32, 2-stage TK=128
// ---------------------------------------------------------------------------
__global__ __launch_bounds__(NTHREADS, 1) void gemm_kernel(float* __restrict__ out) {
    extern __shared__ char smem[];
    const uint32_t sA0 = smem_u32(smem);
    const uint32_t sB0 = sA0 + 2 * A_STAGE_BYTES;

    const int tid = threadIdx.x;
    const int wid = tid >> 5;
    const int lane = tid & 31;
    const int wm = wid & 1;        // 0..1  (64 rows each)
    const int wn = wid >> 1;       // 0..7  (32 cols each)

    const int TILES_N = NN / TN;   // 16
    const int GROUP_M = 8;
    int bid = blockIdx.x;
    int group = bid / (GROUP_M * TILES_N);
    int rem = bid % (GROUP_M * TILES_N);
    int pm = group * GROUP_M + (rem % GROUP_M);
    int pn = rem / GROUP_M;
    const int m0 = pm * TM;
    const int n0 = pn * TN;

    const __half* gA = g_xh + (size_t)m0 * KK;
    const __half* gB = g_sh + (size_t)n0 * KK;

    // stage loader: rows of 256B (16 chunks of 16B), XOR-swizzle low 3 bits
    auto load_stage = [&](int s, int it) {
        uint32_t sa = sA0 + s * A_STAGE_BYTES;
        uint32_t sb = sB0 + s * B_STAGE_BYTES;
        const __half* ga = gA + (size_t)it * TK;
        const __half* gb = gB + (size_t)it * TK;
#pragma unroll
        for (int i = 0; i < 4; ++i) {                 // A: 2048 chunks / 512 thr
            int idx = tid + i * 512;
            int row = idx >> 4, c = idx & 15;
            int sc = c ^ (row & 7);
            CP_ASYNC_CG(sa + row * 256 + sc * 16, ga + (size_t)row * KK + c * 8);
        }
#pragma unroll
        for (int i = 0; i < 8; ++i) {                 // B: 4096 chunks / 512 thr
            int idx = tid + i * 512;
            int row = idx >> 4, c = idx & 15;
            int sc = c ^ (row & 7);
            CP_ASYNC_CG(sb + row * 256 + sc * 16, gb + (size_t)row * KK + c * 8);
        }
    };

    const int a_row_base = wm * 64 + (lane & 15);
    const int a_hi = lane >> 4;
    const int b_n_base = wn * 32 + (lane & 7) + ((lane >> 4) << 3);
    const int b_hi = (lane >> 3) & 1;

    float acc[4][4][4];
#pragma unroll
    for (int mt = 0; mt < 4; ++mt)
#pragma unroll
        for (int nf = 0; nf < 4; ++nf)
#pragma unroll
            for (int v = 0; v < 4; ++v) acc[mt][nf][v] = 0.f;

    load_stage(0, 0);
    CP_COMMIT();

    for (int it = 0; it < NK; ++it) {
        CP_WAIT(0);
        __syncthreads();

        if (it + 1 < NK) load_stage((it + 1) & 1, it + 1);
        CP_COMMIT();

        const int s = it & 1;
        const uint32_t sa = sA0 + s * A_STAGE_BYTES;
        const uint32_t sb = sB0 + s * B_STAGE_BYTES;

#pragma unroll
        for (int ks = 0; ks < 8; ++ks) {
            uint32_t a[4][4], b[2][4];
#pragma unroll
            for (int mt = 0; mt < 4; ++mt) {
                int row = a_row_base + mt * 16;
                int ch = ks * 2 + a_hi;
                ldsm4(a[mt], sa + row * 256 + ((ch ^ (row & 7)) << 4));
            }
#pragma unroll
            for (int bq = 0; bq < 2; ++bq) {
                int n = b_n_base + bq * 16;
                int ch = ks * 2 + b_hi;
                ldsm4(b[bq], sb + n * 256 + ((ch ^ (n & 7)) << 4));
            }
#pragma unroll
            for (int mt = 0; mt < 4; ++mt)
#pragma unroll
                for (int nf = 0; nf < 4; ++nf)
                    mma16816(acc[mt][nf], a[mt], &b[nf >> 1][(nf & 1) * 2]);
        }
    }

    // epilogue: direct float2 stores
#pragma unroll
    for (int mt = 0; mt < 4; ++mt) {
        int r0 = m0 + wm * 64 + mt * 16 + (lane >> 2);
#pragma unroll
        for (int nf = 0; nf < 4; ++nf) {
            int c0 = n0 + wn * 32 + nf * 8 + (lane & 3) * 2;
            float2 v0 = make_float2(acc[mt][nf][0], acc[mt][nf][1]);
            float2 v1 = make_float2(acc[mt][nf][2], acc[mt][nf][3]);
            *reinterpret_cast<float2*>(out + (size_t)r0 * NN + c0) = v0;
            *reinterpret_cast<float2*>(out + (size_t)(r0 + 8) * NN + c0) = v1;
        }
    }
}

// ---------------------------------------------------------------------------
extern "C" void kernel_launch(void* const* d_in, const int* in_sizes, int n_in,
                              void* d_out, int out_size) {
    const float* x;
    const float* W;
    if (in_sizes[0] == MM * KK) {
        x = (const float*)d_in[0];
        W = (const float*)d_in[1];
    } else {
        x = (const float*)d_in[1];
        W = (const float*)d_in[0];
    }

    void* xh_ptr = nullptr;
    void* sh_ptr = nullptr;
    cudaGetSymbolAddress(&xh_ptr, g_xh);
    cudaGetSymbolAddress(&sh_ptr, g_sh);

    {
        int n8 = MM * KK / 8;
        k_cvt_x<<<(n8 + 255) / 256, 256>>>((const float4*)x, (h8_t*)xh_ptr, n8);
        dim3 g(NN / 64, KK / 64), b(64, 4);
        k_sign_t<<<g, b>>>(W, (__half*)sh_ptr);
    }

    cudaFuncSetAttribute(gemm_kernel, cudaFuncAttributeMaxDynamicSharedMemorySize, SMEM_TOTAL);
    int n_tiles = (MM / TM) * (NN / TN);   // 1024
    gemm_kernel<<<n_tiles, NTHREADS, SMEM_TOTAL>>>((float*)d_out);
}

// round 9
// speedup vs baseline: 3.3739x; 1.0526x over previous
#include <cuda_runtime.h>
#include <cuda_fp16.h>
#include <cstdint>

// ============================================================================
// y[8192,4096] = x[8192,4096] @ sign(W)[4096,4096], fp32 in/out.
// Plain-sm_103 target (no tcgen05). Pipelined HMMA GEMM.
// R9: 2 CTAs/SM. CTA tile 128x128, 256 threads / 8 warps (2M x 4N),
// warp tile 64x32, TK=64, 3 stages, 96KB smem/CTA, <=128 regs/thread.
// Same per-SM crossbar+HMMA work as R8; pure overlap play (two independent
// CTAs interleave LDSM bursts with MMA drains; barriers couple only 8 warps).
// ============================================================================

#define MM 8192
#define NN 4096
#define KK 4096

#define TM 128
#define TN 128
#define TK 64                      // K elems per stage (128B per row)
#define NSTAGE 3
#define NK (KK / TK)               // 64

#define A_STAGE_BYTES (TM * TK * 2)            // 16384
#define B_STAGE_BYTES (TN * TK * 2)            // 16384
#define SMEM_TOTAL (NSTAGE * (A_STAGE_BYTES + B_STAGE_BYTES))  // 98304

#define NTHREADS 256

__device__ __align__(1024) __half g_xh[(size_t)MM * KK];   // x as fp16, [M][K]
__device__ __align__(1024) __half g_sh[(size_t)NN * KK];   // sign(W)^T fp16, [N][K]

// ---------------------------------------------------------------------------
__device__ __forceinline__ uint32_t smem_u32(const void* p) {
    uint32_t a;
    asm("{ .reg .u64 t; cvta.to.shared.u64 t, %1; cvt.u32.u64 %0, t; }"
        : "=r"(a) : "l"(p));
    return a;
}

#define CP_ASYNC_CG(dst, src) \
    asm volatile("cp.async.cg.shared.global [%0], [%1], 16;" \
        :: "r"((uint32_t)(dst)), "l"(src) : "memory")
#define CP_COMMIT() asm volatile("cp.async.commit_group;" ::: "memory")
#define CP_WAIT(n)  asm volatile("cp.async.wait_group %0;" :: "n"(n) : "memory")

__device__ __forceinline__ void ldsm4(uint32_t* r, uint32_t addr) {
    asm volatile("ldmatrix.sync.aligned.m8n8.x4.shared.b16 {%0,%1,%2,%3}, [%4];"
        : "=r"(r[0]), "=r"(r[1]), "=r"(r[2]), "=r"(r[3]) : "r"(addr));
}

__device__ __forceinline__ void mma16816(float* c, const uint32_t* a, const uint32_t* b) {
    asm volatile(
        "mma.sync.aligned.m16n8k16.row.col.f32.f16.f16.f32 "
        "{%0,%1,%2,%3}, {%4,%5,%6,%7}, {%8,%9}, {%0,%1,%2,%3};"
        : "+f"(c[0]), "+f"(c[1]), "+f"(c[2]), "+f"(c[3])
        : "r"(a[0]), "r"(a[1]), "r"(a[2]), "r"(a[3]), "r"(b[0]), "r"(b[1]));
}

// ---------------------------------------------------------------------------
struct h8_t { __half2 a, b, c, d; };   // 16B

__global__ void k_cvt_x(const float4* __restrict__ x, h8_t* __restrict__ o, int n8) {
    int i = blockIdx.x * blockDim.x + threadIdx.x;
    if (i < n8) {
        float4 v0 = x[2 * i];
        float4 v1 = x[2 * i + 1];
        h8_t h;
        h.a = __floats2half2_rn(v0.x, v0.y);
        h.b = __floats2half2_rn(v0.z, v0.w);
        h.c = __floats2half2_rn(v1.x, v1.y);
        h.d = __floats2half2_rn(v1.z, v1.w);
        o[i] = h;
    }
}

// o[n][k] = sign(W[k][n]) fp16; 64x64 tiles -> 128B coalesced output rows
__global__ void k_sign_t(const float* __restrict__ W, __half* __restrict__ o) {
    __shared__ float t[64][65];
    int n0 = blockIdx.x * 64, k0 = blockIdx.y * 64;
    int tx = threadIdx.x, ty = threadIdx.y;    // (64, 4)
#pragma unroll
    for (int j = 0; j < 64; j += 4)
        t[ty + j][tx] = W[(size_t)(k0 + ty + j) * NN + n0 + tx];
    __syncthreads();
#pragma unroll
    for (int j = 0; j < 64; j += 4) {
        float v = t[tx][ty + j];
        float s = (v > 0.f) ? 1.f : ((v < 0.f) ? -1.f : 0.f);
        o[(size_t)(n0 + ty + j) * KK + k0 + tx] = __float2half(s);
    }
}

// ---------------------------------------------------------------------------
// GEMM: 128x128 CTA tile, 8 warps (2M x 4N), warp tile 64x32, 3-stage TK=64
// ---------------------------------------------------------------------------
__global__ __launch_bounds__(NTHREADS, 2) void gemm_kernel(float* __restrict__ out) {
    extern __shared__ char smem[];
    const uint32_t sA0 = smem_u32(smem);
    const uint32_t sB0 = sA0 + NSTAGE * A_STAGE_BYTES;

    const int tid = threadIdx.x;
    const int wid = tid >> 5;
    const int lane = tid & 31;
    const int wm = wid & 1;        // 0..1  (64 rows each)
    const int wn = wid >> 1;       // 0..3  (32 cols each)

    const int TILES_N = NN / TN;   // 32
    const int GROUP_M = 8;
    int bid = blockIdx.x;
    int group = bid / (GROUP_M * TILES_N);
    int rem = bid % (GROUP_M * TILES_N);
    int pm = group * GROUP_M + (rem % GROUP_M);
    int pn = rem / GROUP_M;
    const int m0 = pm * TM;
    const int n0 = pn * TN;

    const __half* gA = g_xh + (size_t)m0 * KK;
    const __half* gB = g_sh + (size_t)n0 * KK;

    // stage loader: 128 rows x 128B per operand, XOR-swizzled 16B chunks
    auto load_stage = [&](int s, int it) {
        uint32_t sa = sA0 + s * A_STAGE_BYTES;
        uint32_t sb = sB0 + s * B_STAGE_BYTES;
        const __half* ga = gA + (size_t)it * TK;
        const __half* gb = gB + (size_t)it * TK;
#pragma unroll
        for (int i = 0; i < 4; ++i) {                 // A: 1024 chunks / 256 thr
            int idx = tid + i * 256;
            int row = idx >> 3, c = idx & 7;
            int sc = c ^ (row & 7);
            CP_ASYNC_CG(sa + row * 128 + sc * 16, ga + (size_t)row * KK + c * 8);
        }
#pragma unroll
        for (int i = 0; i < 4; ++i) {                 // B: 1024 chunks / 256 thr
            int idx = tid + i * 256;
            int row = idx >> 3, c = idx & 7;
            int sc = c ^ (row & 7);
            CP_ASYNC_CG(sb + row * 128 + sc * 16, gb + (size_t)row * KK + c * 8);
        }
    };

    const int a_row_base = wm * 64 + (lane & 15);
    const int a_hi = lane >> 4;
    const int b_n_base = wn * 32 + (lane & 7) + ((lane >> 4) << 3);
    const int b_hi = (lane >> 3) & 1;

    float acc[4][4][4];
#pragma unroll
    for (int mt = 0; mt < 4; ++mt)
#pragma unroll
        for (int nf = 0; nf < 4; ++nf)
#pragma unroll
            for (int v = 0; v < 4; ++v) acc[mt][nf][v] = 0.f;

#pragma unroll
    for (int s = 0; s < NSTAGE - 1; ++s) {
        load_stage(s, s);
        CP_COMMIT();
    }

    int s_cur = 0, s_nxt = NSTAGE - 1;

    for (int it = 0; it < NK; ++it) {
        CP_WAIT(NSTAGE - 2);
        __syncthreads();

        int nx = it + NSTAGE - 1;
        if (nx < NK) load_stage(s_nxt, nx);
        CP_COMMIT();

        const uint32_t sa = sA0 + s_cur * A_STAGE_BYTES;
        const uint32_t sb = sB0 + s_cur * B_STAGE_BYTES;

#pragma unroll
        for (int ks = 0; ks < 4; ++ks) {
            uint32_t a[4][4], b[2][4];
#pragma unroll
            for (int mt = 0; mt < 4; ++mt) {
                int row = a_row_base + mt * 16;
                int ch = ks * 2 + a_hi;
                ldsm4(a[mt], sa + row * 128 + ((ch ^ (row & 7)) << 4));
            }
#pragma unroll
            for (int bq = 0; bq < 2; ++bq) {
                int n = b_n_base + bq * 16;
                int ch = ks * 2 + b_hi;
                ldsm4(b[bq], sb + n * 128 + ((ch ^ (n & 7)) << 4));
            }
#pragma unroll
            for (int mt = 0; mt < 4; ++mt)
#pragma unroll
                for (int nf = 0; nf < 4; ++nf)
                    mma16816(acc[mt][nf], a[mt], &b[nf >> 1][(nf & 1) * 2]);
        }

        if (++s_cur == NSTAGE) s_cur = 0;
        if (++s_nxt == NSTAGE) s_nxt = 0;
    }

    // epilogue: direct float2 stores
#pragma unroll
    for (int mt = 0; mt < 4; ++mt) {
        int r0 = m0 + wm * 64 + mt * 16 + (lane >> 2);
#pragma unroll
        for (int nf = 0; nf < 4; ++nf) {
            int c0 = n0 + wn * 32 + nf * 8 + (lane & 3) * 2;
            float2 v0 = make_float2(acc[mt][nf][0], acc[mt][nf][1]);
            float2 v1 = make_float2(acc[mt][nf][2], acc[mt][nf][3]);
            *reinterpret_cast<float2*>(out + (size_t)r0 * NN + c0) = v0;
            *reinterpret_cast<float2*>(out + (size_t)(r0 + 8) * NN + c0) = v1;
        }
    }
}

// ---------------------------------------------------------------------------
extern "C" void kernel_launch(void* const* d_in, const int* in_sizes, int n_in,
                              void* d_out, int out_size) {
    const float* x;
    const float* W;
    if (in_sizes[0] == MM * KK) {
        x = (const float*)d_in[0];
        W = (const float*)d_in[1];
    } else {
        x = (const float*)d_in[1];
        W = (const float*)d_in[0];
    }

    void* xh_ptr = nullptr;
    void* sh_ptr = nullptr;
    cudaGetSymbolAddress(&xh_ptr, g_xh);
    cudaGetSymbolAddress(&sh_ptr, g_sh);

    {
        int n8 = MM * KK / 8;
        k_cvt_x<<<(n8 + 255) / 256, 256>>>((const float4*)x, (h8_t*)xh_ptr, n8);
        dim3 g(NN / 64, KK / 64), b(64, 4);
        k_sign_t<<<g, b>>>(W, (__half*)sh_ptr);
    }

    cudaFuncSetAttribute(gemm_kernel, cudaFuncAttributeMaxDynamicSharedMemorySize, SMEM_TOTAL);
    int n_tiles = (MM / TM) * (NN / TN);   // 2048
    gemm_kernel<<<n_tiles, NTHREADS, SMEM_TOTAL>>>((float*)d_out);
}

// round 12
// speedup vs baseline: 3.4629x; 1.0264x over previous
#include <cuda_runtime.h>
#include <cuda_fp16.h>
#include <cstdint>

// ============================================================================
// y[8192,4096] = x[8192,4096] @ sign(W)[4096,4096], fp32 in/out.
// Plain-sm_103 target (no tcgen05). Pipelined HMMA GEMM, 2 CTAs/SM,
// CTA tile 128x128, 8 warps (2M x 4N), warp tile 64x32, TK=64, 3 stages.
// R12 (= R11 + conversion-kernel bounds fix): blobs are 1024 16B chunks,
// write loops were iterating 2048 (OOB reads past input -> illegal access).
// Conversion kernels emit PRE-SWIZZLED 16KB blobs; GEMM loads each stage with
// TWO cp.async.bulk + mbarrier instead of 2048 cp.async + address ALU.
// ============================================================================

#define MM 8192
#define NN 4096
#define KK 4096

#define TM 128
#define TN 128
#define TK 64
#define NSTAGE 3
#define NK (KK / TK)               // 64

#define BLOB_BYTES 16384           // one 128x64 fp16 tile, swizzled
#define BLOB_ELEMS 8192
#define STAGE_BYTES (2 * BLOB_BYTES)
#define SMEM_TILES_OFF 1024
#define SMEM_TOTAL (SMEM_TILES_OFF + NSTAGE * STAGE_BYTES)   // 99328 -> 2 CTAs/SM

#define NTHREADS 256

// Blobbed scratch: A blob (tm,ks) at ((tm*64+ks)*8192) elems; B blob (tn,ks) same.
__device__ __align__(1024) __half g_xh[(size_t)MM * KK];
__device__ __align__(1024) __half g_sh[(size_t)NN * KK];

// ---------------------------------------------------------------------------
__device__ __forceinline__ uint32_t smem_u32(const void* p) {
    uint32_t a;
    asm("{ .reg .u64 t; cvta.to.shared.u64 t, %1; cvt.u32.u64 %0, t; }"
        : "=r"(a) : "l"(p));
    return a;
}

__device__ __forceinline__ uint32_t h2_u32(__half2 h) {
    return reinterpret_cast<uint32_t&>(h);
}

#define MBARRIER_INIT(addr, count) \
    asm volatile("mbarrier.init.shared.b64 [%0], %1;" \
        :: "r"((uint32_t)(addr)), "r"((uint32_t)(count)) : "memory")

#define MBARRIER_EXPECT_TX(addr, bytes) \
    asm volatile("mbarrier.arrive.expect_tx.shared.b64 _, [%0], %1;" \
        :: "r"((uint32_t)(addr)), "r"((uint32_t)(bytes)) : "memory")

#define MBARRIER_WAIT_PARITY(mbar_smem_addr, phase_parity) do { \
    uint32_t _mbar = (uint32_t)(mbar_smem_addr); \
    uint32_t _parity = (uint32_t)(phase_parity); \
    uint32_t _done; \
    asm volatile( \
        "{\n\t.reg .pred p;\n\t" \
        "mbarrier.try_wait.parity.acquire.cta.shared::cta.b64 p, [%1], %2;\n\t" \
        "selp.b32 %0, 1, 0, p;\n\t}" \
        : "=r"(_done) : "r"(_mbar), "r"(_parity) : "memory"); \
    if (!_done) { \
        asm volatile( \
            "{\n\t.reg .pred P1;\n\t" \
            "WAIT_LOOP_%=:\n\t" \
            "mbarrier.try_wait.parity.acquire.cta.shared::cta.b64 P1, [%0], %1, 0x989680;\n\t" \
            "@P1 bra.uni WAIT_DONE_%=;\n\t" \
            "bra.uni WAIT_LOOP_%=;\n\t" \
            "WAIT_DONE_%=:\n\t}" \
            :: "r"(_mbar), "r"(_parity) : "memory"); \
    } \
} while (0)

#define FENCE_PROXY_ASYNC() \
    asm volatile("fence.proxy.async.shared::cta;" ::: "memory")

// Bulk async copy gmem -> smem with mbarrier transaction completion (sm_90).
#define CP_BULK(dst, src, bytes, mbar) \
    asm volatile( \
        "cp.async.bulk.shared::cluster.global.mbarrier::complete_tx::bytes " \
        "[%0], [%1], %2, [%3];" \
        :: "r"((uint32_t)(dst)), "l"(src), "r"((uint32_t)(bytes)), \
           "r"((uint32_t)(mbar)) : "memory")

__device__ __forceinline__ void ldsm4(uint32_t* r, uint32_t addr) {
    asm volatile("ldmatrix.sync.aligned.m8n8.x4.shared.b16 {%0,%1,%2,%3}, [%4];"
        : "=r"(r[0]), "=r"(r[1]), "=r"(r[2]), "=r"(r[3]) : "r"(addr));
}

__device__ __forceinline__ void mma16816(float* c, const uint32_t* a, const uint32_t* b) {
    asm volatile(
        "mma.sync.aligned.m16n8k16.row.col.f32.f16.f16.f32 "
        "{%0,%1,%2,%3}, {%4,%5,%6,%7}, {%8,%9}, {%0,%1,%2,%3};"
        : "+f"(c[0]), "+f"(c[1]), "+f"(c[2]), "+f"(c[3])
        : "r"(a[0]), "r"(a[1]), "r"(a[2]), "r"(a[3]), "r"(b[0]), "r"(b[1]));
}

// ---------------------------------------------------------------------------
// x -> fp16 blobs. Block b: tm = b>>6, ks = b&63. 1024 16B-chunks per blob.
// Chunk (r, c): in = x[tm*128+r][ks*64 + c*8 .. +7]; out at r*128 + (c^(r&7))*16.
// ---------------------------------------------------------------------------
__global__ void k_cvt_x(const float* __restrict__ x, __half* __restrict__ o) {
    int b = blockIdx.x;
    int tm = b >> 6, ks = b & 63;
    const float* src = x + (size_t)tm * 128 * KK + ks * 64;
    char* dst = reinterpret_cast<char*>(o + (size_t)b * BLOB_ELEMS);
    int tid = threadIdx.x;
#pragma unroll
    for (int i = 0; i < 4; ++i) {          // 1024 chunks / 256 threads
        int q = tid + i * 256;
        int r = q >> 3, c = q & 7;         // r: 0..127, c: 0..7
        const float4* s4 = reinterpret_cast<const float4*>(src + (size_t)r * KK + c * 8);
        float4 v0 = s4[0], v1 = s4[1];
        uint4 w;
        w.x = h2_u32(__floats2half2_rn(v0.x, v0.y));
        w.y = h2_u32(__floats2half2_rn(v0.z, v0.w));
        w.z = h2_u32(__floats2half2_rn(v1.x, v1.y));
        w.w = h2_u32(__floats2half2_rn(v1.z, v1.w));
        int sc = c ^ (r & 7);
        *reinterpret_cast<uint4*>(dst + r * 128 + sc * 16) = w;
    }
}

// ---------------------------------------------------------------------------
// sign(W)^T -> fp16 blobs. Block b: tn = b>>6, ks = b&63.
// Loads W[ks*64..+64][tn*128..+128] into smem, emits blob rows = n (0..127).
// ---------------------------------------------------------------------------
__global__ void k_sign_t(const float* __restrict__ W, __half* __restrict__ o) {
    __shared__ float t[64][129];
    int b = blockIdx.x;
    int tn = b >> 6, ks = b & 63;
    const float* src = W + (size_t)ks * 64 * NN + tn * 128;
    char* dst = reinterpret_cast<char*>(o + (size_t)b * BLOB_ELEMS);
    int tid = threadIdx.x;
#pragma unroll
    for (int i = 0; i < 8; ++i) {
        int f = tid + i * 256;          // float4 index, 0..2047 (64 rows x 32)
        int row = f >> 5, c4 = f & 31;
        float4 v = reinterpret_cast<const float4*>(src + (size_t)row * NN)[c4];
        t[row][c4 * 4 + 0] = v.x;
        t[row][c4 * 4 + 1] = v.y;
        t[row][c4 * 4 + 2] = v.z;
        t[row][c4 * 4 + 3] = v.w;
    }
    __syncthreads();
#pragma unroll
    for (int i = 0; i < 4; ++i) {          // 1024 chunks / 256 threads
        int q = tid + i * 256;
        int n = q >> 3, c = q & 7;         // n: 0..127, c: 0..7
        union { __half h[8]; uint4 u; } w;
#pragma unroll
        for (int j = 0; j < 8; ++j) {
            float v = t[c * 8 + j][n];
            float s = (v > 0.f) ? 1.f : ((v < 0.f) ? -1.f : 0.f);
            w.h[j] = __float2half(s);
        }
        int sc = c ^ (n & 7);
        *reinterpret_cast<uint4*>(dst + n * 128 + sc * 16) = w.u;
    }
}

// ---------------------------------------------------------------------------
// GEMM: 128x128 CTA tile, 8 warps (2M x 4N), warp 64x32, 3 stages via bulk DMA
// ---------------------------------------------------------------------------
__global__ __launch_bounds__(NTHREADS, 2) __cluster_dims__(1, 1, 1)
void gemm_kernel(float* __restrict__ out) {
    extern __shared__ char smem[];
    const uint32_t sbase = smem_u32(smem);
    const uint32_t barB = sbase;                       // 3 x 8B mbarriers
    const uint32_t tiles = sbase + SMEM_TILES_OFF;

    const int tid = threadIdx.x;
    const int wid = tid >> 5;
    const int lane = tid & 31;
    const int wm = wid & 1;
    const int wn = wid >> 1;

    const int TILES_N = NN / TN;   // 32
    const int GROUP_M = 8;
    int bid = blockIdx.x;
    int group = bid / (GROUP_M * TILES_N);
    int rem = bid % (GROUP_M * TILES_N);
    int pm = group * GROUP_M + (rem % GROUP_M);
    int pn = rem / GROUP_M;
    const int m0 = pm * TM;
    const int n0 = pn * TN;

    const __half* blobA = g_xh + (size_t)(pm * 64) * BLOB_ELEMS;
    const __half* blobB = g_sh + (size_t)(pn * 64) * BLOB_ELEMS;

    if (tid == 0) {
#pragma unroll
        for (int s = 0; s < NSTAGE; ++s) MBARRIER_INIT(barB + 8 * s, 1);
        FENCE_PROXY_ASYNC();
        // prologue: issue stages 0 and 1
#pragma unroll
        for (int s = 0; s < 2; ++s) {
            uint32_t bar = barB + 8 * s;
            MBARRIER_EXPECT_TX(bar, STAGE_BYTES);
            CP_BULK(tiles + s * STAGE_BYTES,
                    blobA + (size_t)s * BLOB_ELEMS, BLOB_BYTES, bar);
            CP_BULK(tiles + s * STAGE_BYTES + BLOB_BYTES,
                    blobB + (size_t)s * BLOB_ELEMS, BLOB_BYTES, bar);
        }
    }

    const int a_row_base = wm * 64 + (lane & 15);
    const int a_hi = lane >> 4;
    const int b_n_base = wn * 32 + (lane & 7) + ((lane >> 4) << 3);
    const int b_hi = (lane >> 3) & 1;

    float acc[4][4][4];
#pragma unroll
    for (int mt = 0; mt < 4; ++mt)
#pragma unroll
        for (int nf = 0; nf < 4; ++nf)
#pragma unroll
            for (int v = 0; v < 4; ++v) acc[mt][nf][v] = 0.f;

    int s_cur = 0, ph = 0;
    for (int it = 0; it < NK; ++it) {
        __syncthreads();   // all warps done with iter it-1 (stage (it+2)%3 free)

        if (tid == 0 && it + 2 < NK) {
            int sn = s_cur + 2; if (sn >= NSTAGE) sn -= NSTAGE;
            uint32_t bar = barB + 8 * sn;
            MBARRIER_EXPECT_TX(bar, STAGE_BYTES);
            CP_BULK(tiles + sn * STAGE_BYTES,
                    blobA + (size_t)(it + 2) * BLOB_ELEMS, BLOB_BYTES, bar);
            CP_BULK(tiles + sn * STAGE_BYTES + BLOB_BYTES,
                    blobB + (size_t)(it + 2) * BLOB_ELEMS, BLOB_BYTES, bar);
        }

        MBARRIER_WAIT_PARITY(barB + 8 * s_cur, ph);

        const uint32_t sa = tiles + s_cur * STAGE_BYTES;
        const uint32_t sb = sa + BLOB_BYTES;

#pragma unroll
        for (int ks = 0; ks < 4; ++ks) {
            uint32_t a[4][4], b[2][4];
#pragma unroll
            for (int mt = 0; mt < 4; ++mt) {
                int row = a_row_base + mt * 16;
                int ch = ks * 2 + a_hi;
                ldsm4(a[mt], sa + row * 128 + ((ch ^ (row & 7)) << 4));
            }
#pragma unroll
            for (int bq = 0; bq < 2; ++bq) {
                int n = b_n_base + bq * 16;
                int ch = ks * 2 + b_hi;
                ldsm4(b[bq], sb + n * 128 + ((ch ^ (n & 7)) << 4));
            }
#pragma unroll
            for (int mt = 0; mt < 4; ++mt)
#pragma unroll
                for (int nf = 0; nf < 4; ++nf)
                    mma16816(acc[mt][nf], a[mt], &b[nf >> 1][(nf & 1) * 2]);
        }

        if (++s_cur == NSTAGE) { s_cur = 0; ph ^= 1; }
    }

    // epilogue
#pragma unroll
    for (int mt = 0; mt < 4; ++mt) {
        int r0 = m0 + wm * 64 + mt * 16 + (lane >> 2);
#pragma unroll
        for (int nf = 0; nf < 4; ++nf) {
            int c0 = n0 + wn * 32 + nf * 8 + (lane & 3) * 2;
            float2 v0 = make_float2(acc[mt][nf][0], acc[mt][nf][1]);
            float2 v1 = make_float2(acc[mt][nf][2], acc[mt][nf][3]);
            *reinterpret_cast<float2*>(out + (size_t)r0 * NN + c0) = v0;
            *reinterpret_cast<float2*>(out + (size_t)(r0 + 8) * NN + c0) = v1;
        }
    }
}

// ---------------------------------------------------------------------------
extern "C" void kernel_launch(void* const* d_in, const int* in_sizes, int n_in,
                              void* d_out, int out_size) {
    const float* x;
    const float* W;
    if (in_sizes[0] == MM * KK) {
        x = (const float*)d_in[0];
        W = (const float*)d_in[1];
    } else {
        x = (const float*)d_in[1];
        W = (const float*)d_in[0];
    }

    void* xh_ptr = nullptr;
    void* sh_ptr = nullptr;
    cudaGetSymbolAddress(&xh_ptr, g_xh);
    cudaGetSymbolAddress(&sh_ptr, g_sh);

    k_cvt_x<<<(MM / 128) * (KK / 64), 256>>>(x, (__half*)xh_ptr);      // 4096 blocks
    k_sign_t<<<(NN / 128) * (KK / 64), 256>>>(W, (__half*)sh_ptr);     // 2048 blocks

    cudaFuncSetAttribute(gemm_kernel, cudaFuncAttributeMaxDynamicSharedMemorySize, SMEM_TOTAL);
    int n_tiles = (MM / TM) * (NN / TN);   // 2048
    gemm_kernel<<<n_tiles, NTHREADS, SMEM_TOTAL>>>((float*)d_out);
}

// round 13
// speedup vs baseline: 3.7188x; 1.0739x over previous
#include <cuda_runtime.h>
#include <cuda_fp16.h>
#include <cstdint>

// ============================================================================
// y[8192,4096] = x[8192,4096] @ sign(W)[4096,4096], fp32 in/out.
// Plain-sm_103 target (no tcgen05). Pipelined HMMA GEMM, 2 CTAs/SM,
// CTA tile 128x128, 8 warps (2M x 4N), warp tile 64x32, TK=64, 3 stages,
// stages filled by cp.async.bulk from pre-swizzled blobs.
// R13: per-stage producer/consumer mbarrier ring replaces the per-iteration
// __syncthreads (8-warp convoy + serialized refill). Consumers free-run up to
// 2 stages ahead; producer re-arms a stage after 8 warp-arrivals on empty[s].
// ============================================================================

#define MM 8192
#define NN 4096
#define KK 4096

#define TM 128
#define TN 128
#define TK 64
#define NSTAGE 3
#define NK (KK / TK)               // 64

#define BLOB_BYTES 16384           // one 128x64 fp16 tile, swizzled
#define BLOB_ELEMS 8192
#define STAGE_BYTES (2 * BLOB_BYTES)
#define SMEM_TILES_OFF 1024
#define SMEM_TOTAL (SMEM_TILES_OFF + NSTAGE * STAGE_BYTES)   // 99328 -> 2 CTAs/SM

#define NTHREADS 256

// Blobbed scratch: A blob (tm,ks) at ((tm*64+ks)*8192) elems; B blob (tn,ks) same.
__device__ __align__(1024) __half g_xh[(size_t)MM * KK];
__device__ __align__(1024) __half g_sh[(size_t)NN * KK];

// ---------------------------------------------------------------------------
__device__ __forceinline__ uint32_t smem_u32(const void* p) {
    uint32_t a;
    asm("{ .reg .u64 t; cvta.to.shared.u64 t, %1; cvt.u32.u64 %0, t; }"
        : "=r"(a) : "l"(p));
    return a;
}

__device__ __forceinline__ uint32_t h2_u32(__half2 h) {
    return reinterpret_cast<uint32_t&>(h);
}

#define MBARRIER_INIT(addr, count) \
    asm volatile("mbarrier.init.shared.b64 [%0], %1;" \
        :: "r"((uint32_t)(addr)), "r"((uint32_t)(count)) : "memory")

#define MBARRIER_EXPECT_TX(addr, bytes) \
    asm volatile("mbarrier.arrive.expect_tx.shared.b64 _, [%0], %1;" \
        :: "r"((uint32_t)(addr)), "r"((uint32_t)(bytes)) : "memory")

#define MBARRIER_ARRIVE(addr) \
    asm volatile("mbarrier.arrive.shared.b64 _, [%0];" \
        :: "r"((uint32_t)(addr)) : "memory")

#define MBARRIER_WAIT_PARITY(mbar_smem_addr, phase_parity) do { \
    uint32_t _mbar = (uint32_t)(mbar_smem_addr); \
    uint32_t _parity = (uint32_t)(phase_parity); \
    uint32_t _done; \
    asm volatile( \
        "{\n\t.reg .pred p;\n\t" \
        "mbarrier.try_wait.parity.acquire.cta.shared::cta.b64 p, [%1], %2;\n\t" \
        "selp.b32 %0, 1, 0, p;\n\t}" \
        : "=r"(_done) : "r"(_mbar), "r"(_parity) : "memory"); \
    if (!_done) { \
        asm volatile( \
            "{\n\t.reg .pred P1;\n\t" \
            "WAIT_LOOP_%=:\n\t" \
            "mbarrier.try_wait.parity.acquire.cta.shared::cta.b64 P1, [%0], %1, 0x989680;\n\t" \
            "@P1 bra.uni WAIT_DONE_%=;\n\t" \
            "bra.uni WAIT_LOOP_%=;\n\t" \
            "WAIT_DONE_%=:\n\t}" \
            :: "r"(_mbar), "r"(_parity) : "memory"); \
    } \
} while (0)

#define FENCE_PROXY_ASYNC() \
    asm volatile("fence.proxy.async.shared::cta;" ::: "memory")

// Bulk async copy gmem -> smem with mbarrier transaction completion (sm_90).
#define CP_BULK(dst, src, bytes, mbar) \
    asm volatile( \
        "cp.async.bulk.shared::cluster.global.mbarrier::complete_tx::bytes " \
        "[%0], [%1], %2, [%3];" \
        :: "r"((uint32_t)(dst)), "l"(src), "r"((uint32_t)(bytes)), \
           "r"((uint32_t)(mbar)) : "memory")

__device__ __forceinline__ void ldsm4(uint32_t* r, uint32_t addr) {
    asm volatile("ldmatrix.sync.aligned.m8n8.x4.shared.b16 {%0,%1,%2,%3}, [%4];"
        : "=r"(r[0]), "=r"(r[1]), "=r"(r[2]), "=r"(r[3]) : "r"(addr));
}

__device__ __forceinline__ void mma16816(float* c, const uint32_t* a, const uint32_t* b) {
    asm volatile(
        "mma.sync.aligned.m16n8k16.row.col.f32.f16.f16.f32 "
        "{%0,%1,%2,%3}, {%4,%5,%6,%7}, {%8,%9}, {%0,%1,%2,%3};"
        : "+f"(c[0]), "+f"(c[1]), "+f"(c[2]), "+f"(c[3])
        : "r"(a[0]), "r"(a[1]), "r"(a[2]), "r"(a[3]), "r"(b[0]), "r"(b[1]));
}

// ---------------------------------------------------------------------------
// x -> fp16 blobs. Block b: tm = b>>6, ks = b&63. 1024 16B-chunks per blob.
// ---------------------------------------------------------------------------
__global__ void k_cvt_x(const float* __restrict__ x, __half* __restrict__ o) {
    int b = blockIdx.x;
    int tm = b >> 6, ks = b & 63;
    const float* src = x + (size_t)tm * 128 * KK + ks * 64;
    char* dst = reinterpret_cast<char*>(o + (size_t)b * BLOB_ELEMS);
    int tid = threadIdx.x;
#pragma unroll
    for (int i = 0; i < 4; ++i) {          // 1024 chunks / 256 threads
        int q = tid + i * 256;
        int r = q >> 3, c = q & 7;         // r: 0..127, c: 0..7
        const float4* s4 = reinterpret_cast<const float4*>(src + (size_t)r * KK + c * 8);
        float4 v0 = s4[0], v1 = s4[1];
        uint4 w;
        w.x = h2_u32(__floats2half2_rn(v0.x, v0.y));
        w.y = h2_u32(__floats2half2_rn(v0.z, v0.w));
        w.z = h2_u32(__floats2half2_rn(v1.x, v1.y));
        w.w = h2_u32(__floats2half2_rn(v1.z, v1.w));
        int sc = c ^ (r & 7);
        *reinterpret_cast<uint4*>(dst + r * 128 + sc * 16) = w;
    }
}

// ---------------------------------------------------------------------------
// sign(W)^T -> fp16 blobs. Block b: tn = b>>6, ks = b&63.
// ---------------------------------------------------------------------------
__global__ void k_sign_t(const float* __restrict__ W, __half* __restrict__ o) {
    __shared__ float t[64][129];
    int b = blockIdx.x;
    int tn = b >> 6, ks = b & 63;
    const float* src = W + (size_t)ks * 64 * NN + tn * 128;
    char* dst = reinterpret_cast<char*>(o + (size_t)b * BLOB_ELEMS);
    int tid = threadIdx.x;
#pragma unroll
    for (int i = 0; i < 8; ++i) {
        int f = tid + i * 256;          // float4 index, 0..2047 (64 rows x 32)
        int row = f >> 5, c4 = f & 31;
        float4 v = reinterpret_cast<const float4*>(src + (size_t)row * NN)[c4];
        t[row][c4 * 4 + 0] = v.x;
        t[row][c4 * 4 + 1] = v.y;
        t[row][c4 * 4 + 2] = v.z;
        t[row][c4 * 4 + 3] = v.w;
    }
    __syncthreads();
#pragma unroll
    for (int i = 0; i < 4; ++i) {          // 1024 chunks / 256 threads
        int q = tid + i * 256;
        int n = q >> 3, c = q & 7;         // n: 0..127, c: 0..7
        union { __half h[8]; uint4 u; } w;
#pragma unroll
        for (int j = 0; j < 8; ++j) {
            float v = t[c * 8 + j][n];
            float s = (v > 0.f) ? 1.f : ((v < 0.f) ? -1.f : 0.f);
            w.h[j] = __float2half(s);
        }
        int sc = c ^ (n & 7);
        *reinterpret_cast<uint4*>(dst + n * 128 + sc * 16) = w.u;
    }
}

// ---------------------------------------------------------------------------
// GEMM: 128x128 CTA tile, 8 warps (2M x 4N), warp 64x32, bulk DMA + mbar ring
// ---------------------------------------------------------------------------
__global__ __launch_bounds__(NTHREADS, 2) __cluster_dims__(1, 1, 1)
void gemm_kernel(float* __restrict__ out) {
    extern __shared__ char smem[];
    const uint32_t sbase = smem_u32(smem);
    const uint32_t fullB  = sbase;          // full[3]  at +0,+8,+16
    const uint32_t emptyB = sbase + 24;     // empty[3] at +24,+32,+40
    const uint32_t tiles = sbase + SMEM_TILES_OFF;

    const int tid = threadIdx.x;
    const int wid = tid >> 5;
    const int lane = tid & 31;
    const int wm = wid & 1;
    const int wn = wid >> 1;

    const int TILES_N = NN / TN;   // 32
    const int GROUP_M = 8;
    int bid = blockIdx.x;
    int group = bid / (GROUP_M * TILES_N);
    int rem = bid % (GROUP_M * TILES_N);
    int pm = group * GROUP_M + (rem % GROUP_M);
    int pn = rem / GROUP_M;
    const int m0 = pm * TM;
    const int n0 = pn * TN;

    const __half* blobA = g_xh + (size_t)(pm * 64) * BLOB_ELEMS;
    const __half* blobB = g_sh + (size_t)(pn * 64) * BLOB_ELEMS;

    if (tid == 0) {
#pragma unroll
        for (int s = 0; s < NSTAGE; ++s) {
            MBARRIER_INIT(fullB + 8 * s, 1);
            MBARRIER_INIT(emptyB + 8 * s, 8);       // one arrive per warp
        }
        FENCE_PROXY_ASYNC();
    }
    __syncthreads();        // barrier inits visible to all warps

    if (tid == 0) {
        // prologue: issue stages 0 and 1
#pragma unroll
        for (int s = 0; s < 2; ++s) {
            uint32_t bar = fullB + 8 * s;
            MBARRIER_EXPECT_TX(bar, STAGE_BYTES);
            CP_BULK(tiles + s * STAGE_BYTES,
                    blobA + (size_t)s * BLOB_ELEMS, BLOB_BYTES, bar);
            CP_BULK(tiles + s * STAGE_BYTES + BLOB_BYTES,
                    blobB + (size_t)s * BLOB_ELEMS, BLOB_BYTES, bar);
        }
    }

    const int a_row_base = wm * 64 + (lane & 15);
    const int a_hi = lane >> 4;
    const int b_n_base = wn * 32 + (lane & 7) + ((lane >> 4) << 3);
    const int b_hi = (lane >> 3) & 1;

    float acc[4][4][4];
#pragma unroll
    for (int mt = 0; mt < 4; ++mt)
#pragma unroll
        for (int nf = 0; nf < 4; ++nf)
#pragma unroll
            for (int v = 0; v < 4; ++v) acc[mt][nf][v] = 0.f;

    int s_cur = 0, ph = 0;     // consumer: stage + full-parity
    int es = 0, eph = 0;       // producer: empty-wait stage-counter + parity

    for (int it = 0; it < NK; ++it) {
        // ---- producer (tid 0): re-arm stage (it+2) ----
        if (tid == 0 && it + 2 < NK) {
            int sn = s_cur + 2; if (sn >= NSTAGE) sn -= NSTAGE;
            if (it >= 1) {
                // wait for all 8 warps to have finished reading round-old data
                MBARRIER_WAIT_PARITY(emptyB + 8 * sn, eph);
                if (++es == NSTAGE) { es = 0; eph ^= 1; }
            }
            uint32_t bar = fullB + 8 * sn;
            MBARRIER_EXPECT_TX(bar, STAGE_BYTES);
            CP_BULK(tiles + sn * STAGE_BYTES,
                    blobA + (size_t)(it + 2) * BLOB_ELEMS, BLOB_BYTES, bar);
            CP_BULK(tiles + sn * STAGE_BYTES + BLOB_BYTES,
                    blobB + (size_t)(it + 2) * BLOB_ELEMS, BLOB_BYTES, bar);
        }

        // ---- consumer: wait own stage, compute ----
        MBARRIER_WAIT_PARITY(fullB + 8 * s_cur, ph);

        const uint32_t sa = tiles + s_cur * STAGE_BYTES;
        const uint32_t sb = sa + BLOB_BYTES;

#pragma unroll
        for (int ks = 0; ks < 4; ++ks) {
            uint32_t a[4][4], b[2][4];
#pragma unroll
            for (int mt = 0; mt < 4; ++mt) {
                int row = a_row_base + mt * 16;
                int ch = ks * 2 + a_hi;
                ldsm4(a[mt], sa + row * 128 + ((ch ^ (row & 7)) << 4));
            }
#pragma unroll
            for (int bq = 0; bq < 2; ++bq) {
                int n = b_n_base + bq * 16;
                int ch = ks * 2 + b_hi;
                ldsm4(b[bq], sb + n * 128 + ((ch ^ (n & 7)) << 4));
            }
#pragma unroll
            for (int mt = 0; mt < 4; ++mt)
#pragma unroll
                for (int nf = 0; nf < 4; ++nf)
                    mma16816(acc[mt][nf], a[mt], &b[nf >> 1][(nf & 1) * 2]);
        }

        // ---- signal this warp is done reading stage s_cur ----
        __syncwarp();
        if (lane == 0) MBARRIER_ARRIVE(emptyB + 8 * s_cur);

        if (++s_cur == NSTAGE) { s_cur = 0; ph ^= 1; }
    }

    // epilogue
#pragma unroll
    for (int mt = 0; mt < 4; ++mt) {
        int r0 = m0 + wm * 64 + mt * 16 + (lane >> 2);
#pragma unroll
        for (int nf = 0; nf < 4; ++nf) {
            int c0 = n0 + wn * 32 + nf * 8 + (lane & 3) * 2;
            float2 v0 = make_float2(acc[mt][nf][0], acc[mt][nf][1]);
            float2 v1 = make_float2(acc[mt][nf][2], acc[mt][nf][3]);
            *reinterpret_cast<float2*>(out + (size_t)r0 * NN + c0) = v0;
            *reinterpret_cast<float2*>(out + (size_t)(r0 + 8) * NN + c0) = v1;
        }
    }
}

// ---------------------------------------------------------------------------
extern "C" void kernel_launch(void* const* d_in, const int* in_sizes, int n_in,
                              void* d_out, int out_size) {
    const float* x;
    const float* W;
    if (in_sizes[0] == MM * KK) {
        x = (const float*)d_in[0];
        W = (const float*)d_in[1];
    } else {
        x = (const float*)d_in[1];
        W = (const float*)d_in[0];
    }

    void* xh_ptr = nullptr;
    void* sh_ptr = nullptr;
    cudaGetSymbolAddress(&xh_ptr, g_xh);
    cudaGetSymbolAddress(&sh_ptr, g_sh);

    k_cvt_x<<<(MM / 128) * (KK / 64), 256>>>(x, (__half*)xh_ptr);      // 4096 blocks
    k_sign_t<<<(NN / 128) * (KK / 64), 256>>>(W, (__half*)sh_ptr);     // 2048 blocks

    cudaFuncSetAttribute(gemm_kernel, cudaFuncAttributeMaxDynamicSharedMemorySize, SMEM_TOTAL);
    int n_tiles = (MM / TM) * (NN / TN);   // 2048
    gemm_kernel<<<n_tiles, NTHREADS, SMEM_TOTAL>>>((float*)d_out);
}

// round 14
// speedup vs baseline: 3.7634x; 1.0120x over previous
#include <cuda_runtime.h>
#include <cuda_fp16.h>
#include <cstdint>

// ============================================================================
// y[8192,4096] = x[8192,4096] @ sign(W)[4096,4096], fp32 in/out.
// Plain-sm_103 target (no tcgen05). Pipelined HMMA GEMM, 2 CTAs/SM,
// CTA tile 128x128, bulk-DMA stages from pre-swizzled blobs, mbarrier ring.
// R14: 4 warps (2x2 grid, warp tile 64x64) instead of 8 (2x4, 64x32):
// A and B each re-read only 2x -> smem-port reads drop 96->64 KB per
// CTA-iter (port floor -23%). Feasible only at 4 warps (acc=128 regs/thread).
// ============================================================================

#define MM 8192
#define NN 4096
#define KK 4096

#define TM 128
#define TN 128
#define TK 64
#define NSTAGE 3
#define NK (KK / TK)               // 64

#define BLOB_BYTES 16384           // one 128x64 fp16 tile, swizzled
#define BLOB_ELEMS 8192
#define STAGE_BYTES (2 * BLOB_BYTES)
#define SMEM_TILES_OFF 1024
#define SMEM_TOTAL (SMEM_TILES_OFF + NSTAGE * STAGE_BYTES)   // 99328 -> 2 CTAs/SM

#define NTHREADS 128               // 4 warps

// Blobbed scratch: A blob (tm,ks) at ((tm*64+ks)*8192) elems; B blob (tn,ks) same.
__device__ __align__(1024) __half g_xh[(size_t)MM * KK];
__device__ __align__(1024) __half g_sh[(size_t)NN * KK];

// ---------------------------------------------------------------------------
__device__ __forceinline__ uint32_t smem_u32(const void* p) {
    uint32_t a;
    asm("{ .reg .u64 t; cvta.to.shared.u64 t, %1; cvt.u32.u64 %0, t; }"
        : "=r"(a) : "l"(p));
    return a;
}

__device__ __forceinline__ uint32_t h2_u32(__half2 h) {
    return reinterpret_cast<uint32_t&>(h);
}

#define MBARRIER_INIT(addr, count) \
    asm volatile("mbarrier.init.shared.b64 [%0], %1;" \
        :: "r"((uint32_t)(addr)), "r"((uint32_t)(count)) : "memory")

#define MBARRIER_EXPECT_TX(addr, bytes) \
    asm volatile("mbarrier.arrive.expect_tx.shared.b64 _, [%0], %1;" \
        :: "r"((uint32_t)(addr)), "r"((uint32_t)(bytes)) : "memory")

#define MBARRIER_ARRIVE(addr) \
    asm volatile("mbarrier.arrive.shared.b64 _, [%0];" \
        :: "r"((uint32_t)(addr)) : "memory")

#define MBARRIER_WAIT_PARITY(mbar_smem_addr, phase_parity) do { \
    uint32_t _mbar = (uint32_t)(mbar_smem_addr); \
    uint32_t _parity = (uint32_t)(phase_parity); \
    uint32_t _done; \
    asm volatile( \
        "{\n\t.reg .pred p;\n\t" \
        "mbarrier.try_wait.parity.acquire.cta.shared::cta.b64 p, [%1], %2;\n\t" \
        "selp.b32 %0, 1, 0, p;\n\t}" \
        : "=r"(_done) : "r"(_mbar), "r"(_parity) : "memory"); \
    if (!_done) { \
        asm volatile( \
            "{\n\t.reg .pred P1;\n\t" \
            "WAIT_LOOP_%=:\n\t" \
            "mbarrier.try_wait.parity.acquire.cta.shared::cta.b64 P1, [%0], %1, 0x989680;\n\t" \
            "@P1 bra.uni WAIT_DONE_%=;\n\t" \
            "bra.uni WAIT_LOOP_%=;\n\t" \
            "WAIT_DONE_%=:\n\t}" \
            :: "r"(_mbar), "r"(_parity) : "memory"); \
    } \
} while (0)

#define FENCE_PROXY_ASYNC() \
    asm volatile("fence.proxy.async.shared::cta;" ::: "memory")

// Bulk async copy gmem -> smem with mbarrier transaction completion (sm_90).
#define CP_BULK(dst, src, bytes, mbar) \
    asm volatile( \
        "cp.async.bulk.shared::cluster.global.mbarrier::complete_tx::bytes " \
        "[%0], [%1], %2, [%3];" \
        :: "r"((uint32_t)(dst)), "l"(src), "r"((uint32_t)(bytes)), \
           "r"((uint32_t)(mbar)) : "memory")

__device__ __forceinline__ void ldsm4(uint32_t* r, uint32_t addr) {
    asm volatile("ldmatrix.sync.aligned.m8n8.x4.shared.b16 {%0,%1,%2,%3}, [%4];"
        : "=r"(r[0]), "=r"(r[1]), "=r"(r[2]), "=r"(r[3]) : "r"(addr));
}

__device__ __forceinline__ void mma16816(float* c, const uint32_t* a, const uint32_t* b) {
    asm volatile(
        "mma.sync.aligned.m16n8k16.row.col.f32.f16.f16.f32 "
        "{%0,%1,%2,%3}, {%4,%5,%6,%7}, {%8,%9}, {%0,%1,%2,%3};"
        : "+f"(c[0]), "+f"(c[1]), "+f"(c[2]), "+f"(c[3])
        : "r"(a[0]), "r"(a[1]), "r"(a[2]), "r"(a[3]), "r"(b[0]), "r"(b[1]));
}

// ---------------------------------------------------------------------------
// x -> fp16 blobs. Block b: tm = b>>6, ks = b&63. 1024 16B-chunks per blob.
// ---------------------------------------------------------------------------
__global__ void k_cvt_x(const float* __restrict__ x, __half* __restrict__ o) {
    int b = blockIdx.x;
    int tm = b >> 6, ks = b & 63;
    const float* src = x + (size_t)tm * 128 * KK + ks * 64;
    char* dst = reinterpret_cast<char*>(o + (size_t)b * BLOB_ELEMS);
    int tid = threadIdx.x;
#pragma unroll
    for (int i = 0; i < 4; ++i) {          // 1024 chunks / 256 threads
        int q = tid + i * 256;
        int r = q >> 3, c = q & 7;         // r: 0..127, c: 0..7
        const float4* s4 = reinterpret_cast<const float4*>(src + (size_t)r * KK + c * 8);
        float4 v0 = s4[0], v1 = s4[1];
        uint4 w;
        w.x = h2_u32(__floats2half2_rn(v0.x, v0.y));
        w.y = h2_u32(__floats2half2_rn(v0.z, v0.w));
        w.z = h2_u32(__floats2half2_rn(v1.x, v1.y));
        w.w = h2_u32(__floats2half2_rn(v1.z, v1.w));
        int sc = c ^ (r & 7);
        *reinterpret_cast<uint4*>(dst + r * 128 + sc * 16) = w;
    }
}

// ---------------------------------------------------------------------------
// sign(W)^T -> fp16 blobs. Block b: tn = b>>6, ks = b&63.
// ---------------------------------------------------------------------------
__global__ void k_sign_t(const float* __restrict__ W, __half* __restrict__ o) {
    __shared__ float t[64][129];
    int b = blockIdx.x;
    int tn = b >> 6, ks = b & 63;
    const float* src = W + (size_t)ks * 64 * NN + tn * 128;
    char* dst = reinterpret_cast<char*>(o + (size_t)b * BLOB_ELEMS);
    int tid = threadIdx.x;
#pragma unroll
    for (int i = 0; i < 8; ++i) {
        int f = tid + i * 256;          // float4 index, 0..2047 (64 rows x 32)
        int row = f >> 5, c4 = f & 31;
        float4 v = reinterpret_cast<const float4*>(src + (size_t)row * NN)[c4];
        t[row][c4 * 4 + 0] = v.x;
        t[row][c4 * 4 + 1] = v.y;
        t[row][c4 * 4 + 2] = v.z;
        t[row][c4 * 4 + 3] = v.w;
    }
    __syncthreads();
#pragma unroll
    for (int i = 0; i < 4; ++i) {          // 1024 chunks / 256 threads
        int q = tid + i * 256;
        int n = q >> 3, c = q & 7;         // n: 0..127, c: 0..7
        union { __half h[8]; uint4 u; } w;
#pragma unroll
        for (int j = 0; j < 8; ++j) {
            float v = t[c * 8 + j][n];
            float s = (v > 0.f) ? 1.f : ((v < 0.f) ? -1.f : 0.f);
            w.h[j] = __float2half(s);
        }
        int sc = c ^ (n & 7);
        *reinterpret_cast<uint4*>(dst + n * 128 + sc * 16) = w.u;
    }
}

// ---------------------------------------------------------------------------
// GEMM: 128x128 CTA tile, 4 warps (2M x 2N), warp 64x64, bulk DMA + mbar ring
// ---------------------------------------------------------------------------
__global__ __launch_bounds__(NTHREADS, 2) __cluster_dims__(1, 1, 1)
void gemm_kernel(float* __restrict__ out) {
    extern __shared__ char smem[];
    const uint32_t sbase = smem_u32(smem);
    const uint32_t fullB  = sbase;          // full[3]  at +0,+8,+16
    const uint32_t emptyB = sbase + 24;     // empty[3] at +24,+32,+40
    const uint32_t tiles = sbase + SMEM_TILES_OFF;

    const int tid = threadIdx.x;
    const int wid = tid >> 5;
    const int lane = tid & 31;
    const int wm = wid & 1;        // 0..1 (64 rows)
    const int wn = wid >> 1;       // 0..1 (64 cols)

    const int TILES_N = NN / TN;   // 32
    const int GROUP_M = 8;
    int bid = blockIdx.x;
    int group = bid / (GROUP_M * TILES_N);
    int rem = bid % (GROUP_M * TILES_N);
    int pm = group * GROUP_M + (rem % GROUP_M);
    int pn = rem / GROUP_M;
    const int m0 = pm * TM;
    const int n0 = pn * TN;

    const __half* blobA = g_xh + (size_t)(pm * 64) * BLOB_ELEMS;
    const __half* blobB = g_sh + (size_t)(pn * 64) * BLOB_ELEMS;

    if (tid == 0) {
#pragma unroll
        for (int s = 0; s < NSTAGE; ++s) {
            MBARRIER_INIT(fullB + 8 * s, 1);
            MBARRIER_INIT(emptyB + 8 * s, 4);       // one arrive per warp
        }
        FENCE_PROXY_ASYNC();
    }
    __syncthreads();        // barrier inits visible to all warps

    if (tid == 0) {
        // prologue: issue stages 0 and 1
#pragma unroll
        for (int s = 0; s < 2; ++s) {
            uint32_t bar = fullB + 8 * s;
            MBARRIER_EXPECT_TX(bar, STAGE_BYTES);
            CP_BULK(tiles + s * STAGE_BYTES,
                    blobA + (size_t)s * BLOB_ELEMS, BLOB_BYTES, bar);
            CP_BULK(tiles + s * STAGE_BYTES + BLOB_BYTES,
                    blobB + (size_t)s * BLOB_ELEMS, BLOB_BYTES, bar);
        }
    }

    const int a_row_base = wm * 64 + (lane & 15);
    const int a_hi = lane >> 4;
    const int b_n_base = wn * 64 + (lane & 7) + ((lane >> 4) << 3);
    const int b_hi = (lane >> 3) & 1;

    float acc[4][8][4];
#pragma unroll
    for (int mt = 0; mt < 4; ++mt)
#pragma unroll
        for (int nf = 0; nf < 8; ++nf)
#pragma unroll
            for (int v = 0; v < 4; ++v) acc[mt][nf][v] = 0.f;

    int s_cur = 0, ph = 0;     // consumer: stage + full-parity
    int es = 0, eph = 0;       // producer: empty-wait parity tracking

    for (int it = 0; it < NK; ++it) {
        // ---- producer (tid 0): re-arm stage (it+2) ----
        if (tid == 0 && it + 2 < NK) {
            int sn = s_cur + 2; if (sn >= NSTAGE) sn -= NSTAGE;
            if (it >= 1) {
                MBARRIER_WAIT_PARITY(emptyB + 8 * sn, eph);
                if (++es == NSTAGE) { es = 0; eph ^= 1; }
            }
            uint32_t bar = fullB + 8 * sn;
            MBARRIER_EXPECT_TX(bar, STAGE_BYTES);
            CP_BULK(tiles + sn * STAGE_BYTES,
                    blobA + (size_t)(it + 2) * BLOB_ELEMS, BLOB_BYTES, bar);
            CP_BULK(tiles + sn * STAGE_BYTES + BLOB_BYTES,
                    blobB + (size_t)(it + 2) * BLOB_ELEMS, BLOB_BYTES, bar);
        }

        // ---- consumer: wait own stage, compute ----
        MBARRIER_WAIT_PARITY(fullB + 8 * s_cur, ph);

        const uint32_t sa = tiles + s_cur * STAGE_BYTES;
        const uint32_t sb = sa + BLOB_BYTES;

#pragma unroll
        for (int ks = 0; ks < 4; ++ks) {
            uint32_t a[4][4], b[4][4];
#pragma unroll
            for (int mt = 0; mt < 4; ++mt) {
                int row = a_row_base + mt * 16;
                int ch = ks * 2 + a_hi;
                ldsm4(a[mt], sa + row * 128 + ((ch ^ (row & 7)) << 4));
            }
#pragma unroll
            for (int bq = 0; bq < 4; ++bq) {
                int n = b_n_base + bq * 16;
                int ch = ks * 2 + b_hi;
                ldsm4(b[bq], sb + n * 128 + ((ch ^ (n & 7)) << 4));
            }
#pragma unroll
            for (int mt = 0; mt < 4; ++mt)
#pragma unroll
                for (int nf = 0; nf < 8; ++nf)
                    mma16816(acc[mt][nf], a[mt], &b[nf >> 1][(nf & 1) * 2]);
        }

        // ---- signal this warp is done reading stage s_cur ----
        __syncwarp();
        if (lane == 0) MBARRIER_ARRIVE(emptyB + 8 * s_cur);

        if (++s_cur == NSTAGE) { s_cur = 0; ph ^= 1; }
    }

    // epilogue
#pragma unroll
    for (int mt = 0; mt < 4; ++mt) {
        int r0 = m0 + wm * 64 + mt * 16 + (lane >> 2);
#pragma unroll
        for (int nf = 0; nf < 8; ++nf) {
            int c0 = n0 + wn * 64 + nf * 8 + (lane & 3) * 2;
            float2 v0 = make_float2(acc[mt][nf][0], acc[mt][nf][1]);
            float2 v1 = make_float2(acc[mt][nf][2], acc[mt][nf][3]);
            *reinterpret_cast<float2*>(out + (size_t)r0 * NN + c0) = v0;
            *reinterpret_cast<float2*>(out + (size_t)(r0 + 8) * NN + c0) = v1;
        }
    }
}

// ---------------------------------------------------------------------------
extern "C" void kernel_launch(void* const* d_in, const int* in_sizes, int n_in,
                              void* d_out, int out_size) {
    const float* x;
    const float* W;
    if (in_sizes[0] == MM * KK) {
        x = (const float*)d_in[0];
        W = (const float*)d_in[1];
    } else {
        x = (const float*)d_in[1];
        W = (const float*)d_in[0];
    }

    void* xh_ptr = nullptr;
    void* sh_ptr = nullptr;
    cudaGetSymbolAddress(&xh_ptr, g_xh);
    cudaGetSymbolAddress(&sh_ptr, g_sh);

    k_cvt_x<<<(MM / 128) * (KK / 64), 256>>>(x, (__half*)xh_ptr);      // 4096 blocks
    k_sign_t<<<(NN / 128) * (KK / 64), 256>>>(W, (__half*)sh_ptr);     // 2048 blocks

    cudaFuncSetAttribute(gemm_kernel, cudaFuncAttributeMaxDynamicSharedMemorySize, SMEM_TOTAL);
    int n_tiles = (MM / TM) * (NN / TN);   // 2048
    gemm_kernel<<<n_tiles, NTHREADS, SMEM_TOTAL>>>((float*)d_out);
}